// round 3
// baseline (speedup 1.0000x reference)
#include <cuda_runtime.h>
#include <cstdint>

// Problem constants
// x: (B=2, C=256, D=32, H=32, W=32); NH=8, KD=VD=64
#define C_IN   256
#define P_TOT  32768      // D*H*W per batch
#define HWX    1024       // H*W

// ---------------- packed f32x2 helpers ----------------
typedef unsigned long long u64t;

__device__ __forceinline__ u64t fma2(u64t a, u64t b, u64t c) {
    u64t d;
    asm("fma.rn.f32x2 %0, %1, %2, %3;" : "=l"(d) : "l"(a), "l"(b), "l"(c));
    return d;
}
__device__ __forceinline__ u64t dup2(float x) {
    u64t d;
    asm("mov.b64 %0, {%1, %1};" : "=l"(d) : "f"(x));
    return d;
}
__device__ __forceinline__ u64t pack2(float x, float y) {
    u64t d;
    asm("mov.b64 %0, {%1, %2};" : "=l"(d) : "f"(x), "f"(y));
    return d;
}
__device__ __forceinline__ float2 unpack2(u64t v) {
    float2 f;
    asm("mov.b64 {%0, %1}, %2;" : "=f"(f.x), "=f"(f.y) : "l"(v));
    return f;
}

// ---------------- scratch (device globals, no allocation) ----------------
// q_s[b][n][qd][c][hw]
__device__ float g_q[33554432];   // 2*8*32*64*1024
// k_s[b][kd][c][hw]
__device__ float g_k[4194304];    // 2*32*64*1024
// v_s[b][kd][c][hw]
__device__ float g_v[4194304];
// split-K partials of S: [bn][chunk][qd][kd]
__device__ float g_sp[524288];    // 16*32*32*32
// attn[bn][qd][kd]
__device__ float g_attn[16384];
// o_s[b][ch][d][hw']  — proj input, torch-reshape permutation already applied
__device__ float g_o[33554432];   // 2*512*32768

// ============================================================
// Kernel 1: fused QKV conv as SGEMM  Y(640 x 32768) = W(640x256) * X(256x32768)
// BM=BN=128, BK=8, 256 threads. 8x8 register tile, packed-pair columns:
// acc2[i][jp] covers rows m0+ih*64+ty*4+i, col-pairs {tx*4, tx*4+2, 64+tx*4, 64+tx*4+2}.
// FFMA2 inner loop + register-prefetch double buffering.
// M-tiles: 0..3 -> q_w rows, tile 4 -> kv_w rows (no straddle).
// ============================================================
__global__ __launch_bounds__(256) void k_qkv(
    const float* __restrict__ x,
    const float* __restrict__ qw, const float* __restrict__ qb,
    const float* __restrict__ kvw, const float* __restrict__ kvb)
{
    __shared__ float Ws[8][132];   // row pitch 528B (16B multiple)
    __shared__ float Xs[8][128];

    const int tid = threadIdx.x;
    const int tx = tid & 15, ty = tid >> 4;
    const int b  = blockIdx.z;
    const int m0 = blockIdx.y << 7;
    const int p0 = blockIdx.x << 7;

    const float* Wsrc;
    int mb;
    if (m0 < 512) { Wsrc = qw;  mb = m0; }
    else          { Wsrc = kvw; mb = m0 - 512; }

    const float* X = x + (size_t)b * C_IN * P_TOT;

    const int wm = tid >> 1;          // 0..127
    const int wk = (tid & 1) << 2;    // 0 or 4
    const int xk = tid >> 5;          // 0..7
    const int xp = (tid & 31) << 2;   // 0..124

    u64t acc2[8][4];
#pragma unroll
    for (int i = 0; i < 8; i++)
#pragma unroll
        for (int j = 0; j < 4; j++) acc2[i][j] = 0ull;

    // prefetch first tile
    float4 wv = *(const float4*)(Wsrc + (size_t)(mb + wm) * C_IN + wk);
    float4 xv = *(const float4*)(X + (size_t)xk * P_TOT + p0 + xp);

    for (int k0 = 0; k0 < C_IN; k0 += 8) {
        Ws[wk + 0][wm] = wv.x;
        Ws[wk + 1][wm] = wv.y;
        Ws[wk + 2][wm] = wv.z;
        Ws[wk + 3][wm] = wv.w;
        *(float4*)(&Xs[xk][xp]) = xv;
        __syncthreads();

        if (k0 + 8 < C_IN) {   // prefetch next tile (overlaps compute)
            wv = *(const float4*)(Wsrc + (size_t)(mb + wm) * C_IN + k0 + 8 + wk);
            xv = *(const float4*)(X + (size_t)(k0 + 8 + xk) * P_TOT + p0 + xp);
        }

#pragma unroll
        for (int kk = 0; kk < 8; kk++) {
            float4 a0 = *(const float4*)(&Ws[kk][ty * 4]);
            float4 a1 = *(const float4*)(&Ws[kk][64 + ty * 4]);
            ulonglong2 b0 = *(const ulonglong2*)(&Xs[kk][tx * 4]);
            ulonglong2 b1 = *(const ulonglong2*)(&Xs[kk][64 + tx * 4]);
            const u64t bp[4] = {b0.x, b0.y, b1.x, b1.y};
            const float av[8] = {a0.x, a0.y, a0.z, a0.w, a1.x, a1.y, a1.z, a1.w};
#pragma unroll
            for (int i = 0; i < 8; i++) {
                const u64t ad = dup2(av[i]);
#pragma unroll
                for (int jp = 0; jp < 4; jp++)
                    acc2[i][jp] = fma2(ad, bp[jp], acc2[i][jp]);
            }
        }
        __syncthreads();
    }

    const int d   = p0 >> 10;       // one d per block (128 | 1024)
    const int hw0 = p0 & 1023;
#pragma unroll
    for (int ih = 0; ih < 2; ih++) {
#pragma unroll
        for (int i = 0; i < 4; i++) {
            const int o = m0 + ih * 64 + ty * 4 + i;
            float bias;
            float* dst;
            if (o < 512) {                      // q channel: n = o>>6, c = o&63
                bias = qb[o];
                const int n = o >> 6, c = o & 63;
                dst = g_q + ((((size_t)b * 8 + n) * 32 + d) * 64 + c) * 1024;
            } else if (o < 576) {               // k channel
                bias = kvb[o - 512];
                const int c = o - 512;
                dst = g_k + (((size_t)b * 32 + d) * 64 + c) * 1024;
            } else {                            // v channel
                bias = kvb[o - 512];
                const int c = o - 576;
                dst = g_v + (((size_t)b * 32 + d) * 64 + c) * 1024;
            }
            const int r = ih * 4 + i;
#pragma unroll
            for (int jh = 0; jh < 2; jh++) {
                const float2 pa = unpack2(acc2[r][jh * 2 + 0]);
                const float2 pbv = unpack2(acc2[r][jh * 2 + 1]);
                float4 v;
                v.x = pa.x + bias;
                v.y = pa.y + bias;
                v.z = pbv.x + bias;
                v.w = pbv.y + bias;
                *(float4*)(&dst[hw0 + jh * 64 + tx * 4]) = v;
            }
        }
    }
}

// ============================================================
// Kernel 2a: S_partial[bn][chunk] = Q(32 x 2048chunk) * K^T  (split-K, deterministic)
// ============================================================
__global__ __launch_bounds__(256) void k_qk()
{
    __shared__ float Qs[32][65];
    __shared__ float Ks[32][65];

    const int tid = threadIdx.x;
    const int tx = tid & 15, ty = tid >> 4;
    const int bn = blockIdx.x;      // b*8+n
    const int chunk = blockIdx.y;   // 0..31
    const int b = bn >> 3;

    const float* Q  = g_q + (size_t)bn * 32 * 65536;  // [qd][f]
    const float* Kp = g_k + (size_t)b  * 32 * 65536;  // [kd][f]
    const int f0 = chunk * 2048;

    float a00 = 0.f, a01 = 0.f, a10 = 0.f, a11 = 0.f;

    for (int ft = 0; ft < 2048; ft += 64) {
#pragma unroll
        for (int e = 0; e < 8; e++) {
            const int idx = tid + e * 256;
            const int r = idx >> 6, fi = idx & 63;
            Qs[r][fi] = Q [(size_t)r * 65536 + f0 + ft + fi];
            Ks[r][fi] = Kp[(size_t)r * 65536 + f0 + ft + fi];
        }
        __syncthreads();
#pragma unroll
        for (int ff = 0; ff < 64; ff++) {
            const float q0 = Qs[ty][ff],      q1 = Qs[ty + 16][ff];
            const float k0 = Ks[tx][ff],      k1 = Ks[tx + 16][ff];
            a00 += q0 * k0; a01 += q0 * k1;
            a10 += q1 * k0; a11 += q1 * k1;
        }
        __syncthreads();
    }

    float* S = g_sp + ((size_t)bn * 32 + chunk) * 1024;  // [qd][kd]
    S[ty * 32 + tx]             = a00;
    S[ty * 32 + tx + 16]        = a01;
    S[(ty + 16) * 32 + tx]      = a10;
    S[(ty + 16) * 32 + tx + 16] = a11;
}

// ============================================================
// Kernel 2b: reduce split-K partials, scale, softmax over kd (warp = one row)
// ============================================================
__global__ __launch_bounds__(1024) void k_softmax()
{
    const int bn = blockIdx.x;
    const int qd = threadIdx.x >> 5;
    const int kd = threadIdx.x & 31;

    float s = 0.f;
    for (int ch = 0; ch < 32; ch++)
        s += g_sp[((size_t)bn * 32 + ch) * 1024 + qd * 32 + kd];
    s *= 0.125f;   // VD^-0.5

    float m = s;
#pragma unroll
    for (int o = 16; o > 0; o >>= 1)
        m = fmaxf(m, __shfl_xor_sync(0xffffffffu, m, o));
    const float e = expf(s - m);
    float sum = e;
#pragma unroll
    for (int o = 16; o > 0; o >>= 1)
        sum += __shfl_xor_sync(0xffffffffu, sum, o);

    g_attn[(size_t)bn * 1024 + qd * 32 + kd] = e / sum;
}

// ============================================================
// Kernel 2c: O = attn * V (FFMA2), written directly in the torch-reshape-permuted
// proj-input layout o_s[b][ch][d][hw'] where, for block channel ch:
//   c = ch & 63, hw%8 = ch>>6, thread t owns g = hw/8 = t, hw' = n*128 + t.
// ============================================================
__global__ __launch_bounds__(128) void k_av()
{
    __shared__ float attn_s[8192];   // [n][qd][kd]
    const int t  = threadIdx.x;      // g = hw/8
    const int ch = blockIdx.x;       // 0..511
    const int b  = blockIdx.y;

    for (int i = t; i < 8192; i += 128)
        attn_s[i] = g_attn[(size_t)b * 8192 + i];
    __syncthreads();

    const int c    = ch & 63;
    const int hwlo = ch >> 6;
    const int hw   = t * 8 + hwlo;

    u64t vp[16];
#pragma unroll
    for (int jp = 0; jp < 16; jp++) {
        const float v0 = g_v[(((size_t)b * 32 + 2 * jp)     * 64 + c) * 1024 + hw];
        const float v1 = g_v[(((size_t)b * 32 + 2 * jp + 1) * 64 + c) * 1024 + hw];
        vp[jp] = pack2(v0, v1);
    }

    float* dst = g_o + ((size_t)b * 512 + ch) * 32768;   // + qd*1024 + hw'
#pragma unroll 2
    for (int n = 0; n < 8; n++) {
        const u64t* arow = (const u64t*)(attn_s + n * 1024);
#pragma unroll 4
        for (int qd = 0; qd < 32; qd++) {
            const u64t* ap = arow + qd * 16;
            u64t acc = 0ull;
#pragma unroll
            for (int jp = 0; jp < 16; jp++)
                acc = fma2(ap[jp], vp[jp], acc);
            const float2 f = unpack2(acc);
            dst[qd * 1024 + n * 128 + t] = f.x + f.y;
        }
    }
}

// ============================================================
// Kernel 3: proj conv as SGEMM: out(256 x 32768) = Wp(256x512) * O(512x32768)
// FFMA2 + register prefetch; fused bias + layer_scale; STG.128 output (B,C,D,H,W).
// ============================================================
__global__ __launch_bounds__(256) void k_proj(
    const float* __restrict__ pw, const float* __restrict__ pb,
    const float* __restrict__ ls, float* __restrict__ out)
{
    __shared__ float Ws[8][132];
    __shared__ float Xs[8][128];

    const int tid = threadIdx.x;
    const int tx = tid & 15, ty = tid >> 4;
    const int b  = blockIdx.z;
    const int m0 = blockIdx.y << 7;
    const int p0 = blockIdx.x << 7;

    const float* X = g_o + (size_t)b * 512 * P_TOT;

    const int wm = tid >> 1;
    const int wk = (tid & 1) << 2;
    const int xk = tid >> 5;
    const int xp = (tid & 31) << 2;

    u64t acc2[8][4];
#pragma unroll
    for (int i = 0; i < 8; i++)
#pragma unroll
        for (int j = 0; j < 4; j++) acc2[i][j] = 0ull;

    float4 wv = *(const float4*)(pw + (size_t)(m0 + wm) * 512 + wk);
    float4 xv = *(const float4*)(X + (size_t)xk * P_TOT + p0 + xp);

    for (int k0 = 0; k0 < 512; k0 += 8) {
        Ws[wk + 0][wm] = wv.x;
        Ws[wk + 1][wm] = wv.y;
        Ws[wk + 2][wm] = wv.z;
        Ws[wk + 3][wm] = wv.w;
        *(float4*)(&Xs[xk][xp]) = xv;
        __syncthreads();

        if (k0 + 8 < 512) {
            wv = *(const float4*)(pw + (size_t)(m0 + wm) * 512 + k0 + 8 + wk);
            xv = *(const float4*)(X + (size_t)(k0 + 8 + xk) * P_TOT + p0 + xp);
        }

#pragma unroll
        for (int kk = 0; kk < 8; kk++) {
            float4 a0 = *(const float4*)(&Ws[kk][ty * 4]);
            float4 a1 = *(const float4*)(&Ws[kk][64 + ty * 4]);
            ulonglong2 b0 = *(const ulonglong2*)(&Xs[kk][tx * 4]);
            ulonglong2 b1 = *(const ulonglong2*)(&Xs[kk][64 + tx * 4]);
            const u64t bp[4] = {b0.x, b0.y, b1.x, b1.y};
            const float av[8] = {a0.x, a0.y, a0.z, a0.w, a1.x, a1.y, a1.z, a1.w};
#pragma unroll
            for (int i = 0; i < 8; i++) {
                const u64t ad = dup2(av[i]);
#pragma unroll
                for (int jp = 0; jp < 4; jp++)
                    acc2[i][jp] = fma2(ad, bp[jp], acc2[i][jp]);
            }
        }
        __syncthreads();
    }

#pragma unroll
    for (int ih = 0; ih < 2; ih++) {
#pragma unroll
        for (int i = 0; i < 4; i++) {
            const int o = m0 + ih * 64 + ty * 4 + i;
            const float bias  = pb[o];
            const float scale = ls[o];
            float* dst = out + ((size_t)(b * 256 + o)) * P_TOT + p0;
            const int r = ih * 4 + i;
#pragma unroll
            for (int jh = 0; jh < 2; jh++) {
                const float2 pa = unpack2(acc2[r][jh * 2 + 0]);
                const float2 pbv = unpack2(acc2[r][jh * 2 + 1]);
                float4 v;
                v.x = (pa.x + bias) * scale;
                v.y = (pa.y + bias) * scale;
                v.z = (pbv.x + bias) * scale;
                v.w = (pbv.y + bias) * scale;
                *(float4*)(&dst[jh * 64 + tx * 4]) = v;
            }
        }
    }
}

// ============================================================
extern "C" void kernel_launch(void* const* d_in, const int* in_sizes, int n_in,
                              void* d_out, int out_size)
{
    const float* x   = (const float*)d_in[0];
    const float* qw  = (const float*)d_in[1];
    const float* qb  = (const float*)d_in[2];
    const float* kvw = (const float*)d_in[3];
    const float* kvb = (const float*)d_in[4];
    const float* pw  = (const float*)d_in[5];
    const float* pb  = (const float*)d_in[6];
    const float* ls  = (const float*)d_in[7];
    float* out = (float*)d_out;

    // 1) QKV conv: grid (Ntiles=256, Mtiles=5, B=2)
    k_qkv<<<dim3(256, 5, 2), 256>>>(x, qw, qb, kvw, kvb);
    // 2a) Q.K^T split-K partials: (bn=16, chunks=32)
    k_qk<<<dim3(16, 32), 256>>>();
    // 2b) reduce + softmax
    k_softmax<<<16, 1024>>>();
    // 2c) attn.V with fused output permutation: (ch=512, b=2)
    k_av<<<dim3(512, 2), 128>>>();
    // 3) proj conv: grid (Ntiles=256, Mtiles=2, B=2)
    k_proj<<<dim3(256, 2, 2), 256>>>(pw, pb, ls, out);
}

// round 14
// speedup vs baseline: 1.6200x; 1.6200x over previous
#include <cuda_runtime.h>
#include <cstdint>

// Problem constants
// x: (B=2, C=256, D=32, H=32, W=32); NH=8, KD=VD=64
#define C_IN   256
#define P_TOT  32768      // D*H*W per batch
#define HWX    1024       // H*W

typedef unsigned long long u64t;

// ---------------- packed f32x2 helpers (k_av) ----------------
__device__ __forceinline__ u64t fma2(u64t a, u64t b, u64t c) {
    u64t d;
    asm("fma.rn.f32x2 %0, %1, %2, %3;" : "=l"(d) : "l"(a), "l"(b), "l"(c));
    return d;
}
__device__ __forceinline__ u64t pack2(float x, float y) {
    u64t d;
    asm("mov.b64 %0, {%1, %2};" : "=l"(d) : "f"(x), "f"(y));
    return d;
}
__device__ __forceinline__ float2 unpack2(u64t v) {
    float2 f;
    asm("mov.b64 {%0, %1}, %2;" : "=f"(f.x), "=f"(f.y) : "l"(v));
    return f;
}

// ---------------- tf32 mma helpers ----------------
__device__ __forceinline__ unsigned f2tf(float f) {
    unsigned u;
    asm("cvt.rna.tf32.f32 %0, %1;" : "=r"(u) : "f"(f));
    return u;
}
__device__ __forceinline__ void mma_tf32(
    float& c0, float& c1, float& c2, float& c3,
    unsigned a0, unsigned a1, unsigned a2, unsigned a3,
    unsigned b0, unsigned b1)
{
    asm volatile(
        "mma.sync.aligned.m16n8k8.row.col.f32.tf32.tf32.f32 "
        "{%0,%1,%2,%3},{%4,%5,%6,%7},{%8,%9},{%0,%1,%2,%3};"
        : "+f"(c0), "+f"(c1), "+f"(c2), "+f"(c3)
        : "r"(a0), "r"(a1), "r"(a2), "r"(a3), "r"(b0), "r"(b1));
}

// ---------------- scratch (device globals, no allocation) ----------------
// q_s[b][n][qd][c][hw]
__device__ float g_q[33554432];   // 2*8*32*64*1024
// k_s[b][kd][c][hw]
__device__ float g_k[4194304];    // 2*32*64*1024
// v_s[b][kd][c][hw]
__device__ float g_v[4194304];
// split-K partials of S: [bn][chunk][qd][kd]
__device__ float g_sp[524288];    // 16*32*32*32
// attn[bn][qd][kd]
__device__ float g_attn[16384];
// o_s[b][ch][d][hw']  — proj input, torch-reshape permutation already applied
__device__ float g_o[33554432];   // 2*512*32768

// ============================================================
// Kernel 1: fused QKV conv as tf32 tensor-core GEMM
//   Y(640 x 32768) = W(640x256) * X(256x32768)
// Block 128x128, BK=16, 256 threads = 8 warps.
// Warp tile 64(M) x 32(N): wm = warp&1 (stride 64), wn = warp>>1 (stride 32),
// 4x4 m16n8k8 MMAs per k8-step (mi*16 rows, ni*8 cols). DOUBLE-BUFFERED smem
// (one BAR per BK step) + register prefetch. smem pitch 136 -> conflict-free.
// M-tiles 0..3 = q_w rows, tile 4 = kv_w rows (no straddle).
// ============================================================
__global__ __launch_bounds__(256) void k_qkv(
    const float* __restrict__ x,
    const float* __restrict__ qw, const float* __restrict__ qb,
    const float* __restrict__ kvw, const float* __restrict__ kvb)
{
    __shared__ unsigned As[2][16][136];   // [buf][k][m] tf32 bits
    __shared__ unsigned Bs[2][16][136];   // [buf][k][n] tf32 bits

    const int tid  = threadIdx.x;
    const int lane = tid & 31;
    const int warp = tid >> 5;
    const int wm = warp & 1;           // m tile (0..1) of 64 rows
    const int wn = warp >> 1;          // n tile (0..3) of 32 cols
    const int b  = blockIdx.z;
    const int m0 = blockIdx.y << 7;
    const int p0 = blockIdx.x << 7;

    const float* Wsrc;
    int mb;
    if (m0 < 512) { Wsrc = qw;  mb = m0; }
    else          { Wsrc = kvw; mb = m0 - 512; }

    const float* X = x + (size_t)b * C_IN * P_TOT;

    // loaders
    const int am = tid >> 1;              // 0..127 (W row)
    const int ak = (tid & 1) << 3;        // 0 or 8 (k offset)
    const int brow = tid >> 5;            // 0..7   (k row; also brow+8)
    const int bcol = (tid & 31) << 2;     // 0..124

    const int NIT = C_IN / 16;            // 16 iterations

    float acc[4][4][4];
#pragma unroll
    for (int i = 0; i < 4; i++)
#pragma unroll
        for (int j = 0; j < 4; j++)
#pragma unroll
            for (int r = 0; r < 4; r++) acc[i][j][r] = 0.f;

    float4 wa0, wa1, xb0, xb1;

    // ---- prologue: tile 0 -> smem buf 0 ----
    wa0 = *(const float4*)(Wsrc + (size_t)(mb + am) * C_IN + ak);
    wa1 = *(const float4*)(Wsrc + (size_t)(mb + am) * C_IN + ak + 4);
    xb0 = *(const float4*)(X + (size_t)brow * P_TOT + p0 + bcol);
    xb1 = *(const float4*)(X + (size_t)(brow + 8) * P_TOT + p0 + bcol);
    {
        As[0][ak + 0][am] = f2tf(wa0.x);
        As[0][ak + 1][am] = f2tf(wa0.y);
        As[0][ak + 2][am] = f2tf(wa0.z);
        As[0][ak + 3][am] = f2tf(wa0.w);
        As[0][ak + 4][am] = f2tf(wa1.x);
        As[0][ak + 5][am] = f2tf(wa1.y);
        As[0][ak + 6][am] = f2tf(wa1.z);
        As[0][ak + 7][am] = f2tf(wa1.w);
        uint4 u0 = make_uint4(f2tf(xb0.x), f2tf(xb0.y), f2tf(xb0.z), f2tf(xb0.w));
        uint4 u1 = make_uint4(f2tf(xb1.x), f2tf(xb1.y), f2tf(xb1.z), f2tf(xb1.w));
        *(uint4*)(&Bs[0][brow][bcol])     = u0;
        *(uint4*)(&Bs[0][brow + 8][bcol]) = u1;
    }
    __syncthreads();
    // prefetch tile 1 into regs
    wa0 = *(const float4*)(Wsrc + (size_t)(mb + am) * C_IN + 16 + ak);
    wa1 = *(const float4*)(Wsrc + (size_t)(mb + am) * C_IN + 16 + ak + 4);
    xb0 = *(const float4*)(X + (size_t)(16 + brow) * P_TOT + p0 + bcol);
    xb1 = *(const float4*)(X + (size_t)(16 + brow + 8) * P_TOT + p0 + bcol);

    for (int it = 0; it < NIT; it++) {
        const int cur = it & 1;
        if (it + 1 < NIT) {
            const int nxt = cur ^ 1;
            // store tile it+1 (in regs) into the other buffer
            As[nxt][ak + 0][am] = f2tf(wa0.x);
            As[nxt][ak + 1][am] = f2tf(wa0.y);
            As[nxt][ak + 2][am] = f2tf(wa0.z);
            As[nxt][ak + 3][am] = f2tf(wa0.w);
            As[nxt][ak + 4][am] = f2tf(wa1.x);
            As[nxt][ak + 5][am] = f2tf(wa1.y);
            As[nxt][ak + 6][am] = f2tf(wa1.z);
            As[nxt][ak + 7][am] = f2tf(wa1.w);
            uint4 u0 = make_uint4(f2tf(xb0.x), f2tf(xb0.y), f2tf(xb0.z), f2tf(xb0.w));
            uint4 u1 = make_uint4(f2tf(xb1.x), f2tf(xb1.y), f2tf(xb1.z), f2tf(xb1.w));
            *(uint4*)(&Bs[nxt][brow][bcol])     = u0;
            *(uint4*)(&Bs[nxt][brow + 8][bcol]) = u1;
            if (it + 2 < NIT) {   // prefetch tile it+2 into regs
                const int k2 = (it + 2) * 16;
                wa0 = *(const float4*)(Wsrc + (size_t)(mb + am) * C_IN + k2 + ak);
                wa1 = *(const float4*)(Wsrc + (size_t)(mb + am) * C_IN + k2 + ak + 4);
                xb0 = *(const float4*)(X + (size_t)(k2 + brow) * P_TOT + p0 + bcol);
                xb1 = *(const float4*)(X + (size_t)(k2 + brow + 8) * P_TOT + p0 + bcol);
            }
        }

#pragma unroll
        for (int ks = 0; ks < 16; ks += 8) {
            unsigned afr[4][4], bfr[4][2];
#pragma unroll
            for (int mi = 0; mi < 4; mi++) {
                const int mr = wm * 64 + mi * 16 + (lane >> 2);   // <= 127
                afr[mi][0] = As[cur][ks + (lane & 3)][mr];
                afr[mi][1] = As[cur][ks + (lane & 3)][mr + 8];
                afr[mi][2] = As[cur][ks + 4 + (lane & 3)][mr];
                afr[mi][3] = As[cur][ks + 4 + (lane & 3)][mr + 8];
            }
#pragma unroll
            for (int ni = 0; ni < 4; ni++) {
                const int nc = wn * 32 + ni * 8 + (lane >> 2);    // <= 127
                bfr[ni][0] = Bs[cur][ks + (lane & 3)][nc];
                bfr[ni][1] = Bs[cur][ks + 4 + (lane & 3)][nc];
            }
#pragma unroll
            for (int mi = 0; mi < 4; mi++)
#pragma unroll
                for (int ni = 0; ni < 4; ni++)
                    mma_tf32(acc[mi][ni][0], acc[mi][ni][1], acc[mi][ni][2], acc[mi][ni][3],
                             afr[mi][0], afr[mi][1], afr[mi][2], afr[mi][3],
                             bfr[ni][0], bfr[ni][1]);
        }
        __syncthreads();
    }

    // epilogue: scatter rows into g_q/g_k/g_v (layout-fused)
    const int d    = p0 >> 10;      // one d per block
    const int hw0  = p0 & 1023;
    const int lrow = lane >> 2;
    const int lcol = (lane & 3) << 1;
#pragma unroll
    for (int mi = 0; mi < 4; mi++) {
#pragma unroll
        for (int h = 0; h < 2; h++) {
            const int o = m0 + wm * 64 + mi * 16 + lrow + h * 8;   // <= m0+127
            float bias;
            float* dst;
            if (o < 512) {                      // q: n = o>>6, c = o&63
                bias = qb[o];
                const int n = o >> 6, c = o & 63;
                dst = g_q + ((((size_t)b * 8 + n) * 32 + d) * 64 + c) * 1024;
            } else if (o < 576) {               // k
                bias = kvb[o - 512];
                const int c = o - 512;
                dst = g_k + (((size_t)b * 32 + d) * 64 + c) * 1024;
            } else {                            // v
                bias = kvb[o - 512];
                const int c = o - 576;
                dst = g_v + (((size_t)b * 32 + d) * 64 + c) * 1024;
            }
            float* base = dst + hw0 + wn * 32 + lcol;
#pragma unroll
            for (int ni = 0; ni < 4; ni++) {
                float2 v;
                v.x = acc[mi][ni][h * 2 + 0] + bias;
                v.y = acc[mi][ni][h * 2 + 1] + bias;
                *(float2*)(base + ni * 8) = v;
            }
        }
    }
}

// ============================================================
// Kernel 2a: S_partial[bn][chunk] = Q(32 x 2048chunk) * K^T  (split-K, fp32)
// ============================================================
__global__ __launch_bounds__(256) void k_qk()
{
    __shared__ float Qs[32][65];
    __shared__ float Ks[32][65];

    const int tid = threadIdx.x;
    const int tx = tid & 15, ty = tid >> 4;
    const int bn = blockIdx.x;      // b*8+n
    const int chunk = blockIdx.y;   // 0..31
    const int b = bn >> 3;

    const float* Q  = g_q + (size_t)bn * 32 * 65536;  // [qd][f]
    const float* Kp = g_k + (size_t)b  * 32 * 65536;  // [kd][f]
    const int f0 = chunk * 2048;

    float a00 = 0.f, a01 = 0.f, a10 = 0.f, a11 = 0.f;

    for (int ft = 0; ft < 2048; ft += 64) {
#pragma unroll
        for (int e = 0; e < 8; e++) {
            const int idx = tid + e * 256;
            const int r = idx >> 6, fi = idx & 63;
            Qs[r][fi] = Q [(size_t)r * 65536 + f0 + ft + fi];
            Ks[r][fi] = Kp[(size_t)r * 65536 + f0 + ft + fi];
        }
        __syncthreads();
#pragma unroll
        for (int ff = 0; ff < 64; ff++) {
            const float q0 = Qs[ty][ff],      q1 = Qs[ty + 16][ff];
            const float k0 = Ks[tx][ff],      k1 = Ks[tx + 16][ff];
            a00 += q0 * k0; a01 += q0 * k1;
            a10 += q1 * k0; a11 += q1 * k1;
        }
        __syncthreads();
    }

    float* S = g_sp + ((size_t)bn * 32 + chunk) * 1024;  // [qd][kd]
    S[ty * 32 + tx]             = a00;
    S[ty * 32 + tx + 16]        = a01;
    S[(ty + 16) * 32 + tx]      = a10;
    S[(ty + 16) * 32 + tx + 16] = a11;
}

// ============================================================
// Kernel 2b: reduce split-K partials, scale, softmax over kd (warp = one row)
// ============================================================
__global__ __launch_bounds__(1024) void k_softmax()
{
    const int bn = blockIdx.x;
    const int qd = threadIdx.x >> 5;
    const int kd = threadIdx.x & 31;

    float s = 0.f;
    for (int ch = 0; ch < 32; ch++)
        s += g_sp[((size_t)bn * 32 + ch) * 1024 + qd * 32 + kd];
    s *= 0.125f;   // VD^-0.5

    float m = s;
#pragma unroll
    for (int o = 16; o > 0; o >>= 1)
        m = fmaxf(m, __shfl_xor_sync(0xffffffffu, m, o));
    const float e = expf(s - m);
    float sum = e;
#pragma unroll
    for (int o = 16; o > 0; o >>= 1)
        sum += __shfl_xor_sync(0xffffffffu, sum, o);

    g_attn[(size_t)bn * 1024 + qd * 32 + kd] = e / sum;
}

// ============================================================
// Kernel 2c: O = attn * V (FFMA2), each thread handles TWO channels (c, c+32)
// so every attn LDS.64 feeds two FMA chains (halves the L1-issue bound).
// Output written in the torch-reshape-permuted proj-input layout:
//   dst channel ch = hwlo*64 + c; thread t owns hw = t*8 + hwlo, hw' = n*128 + t.
// ============================================================
__global__ __launch_bounds__(128) void k_av()
{
    __shared__ float attn_s[8192];   // [n][qd][kd]
    const int t   = threadIdx.x;     // g = hw/8
    const int cb  = blockIdx.x;      // 0..255: (hwlo, cpair)
    const int b   = blockIdx.y;

    for (int i = t; i < 8192; i += 128)
        attn_s[i] = g_attn[(size_t)b * 8192 + i];
    __syncthreads();

    const int cpair = cb & 31;       // c_a = cpair, c_b = cpair+32
    const int hwlo  = cb >> 5;
    const int hw    = t * 8 + hwlo;
    const int ca = cpair, cc = cpair + 32;

    u64t vpa[16], vpb[16];
#pragma unroll
    for (int jp = 0; jp < 16; jp++) {
        const size_t base0 = (((size_t)b * 32 + 2 * jp)     * 64) * 1024 + hw;
        const size_t base1 = (((size_t)b * 32 + 2 * jp + 1) * 64) * 1024 + hw;
        vpa[jp] = pack2(g_v[base0 + (size_t)ca * 1024], g_v[base1 + (size_t)ca * 1024]);
        vpb[jp] = pack2(g_v[base0 + (size_t)cc * 1024], g_v[base1 + (size_t)cc * 1024]);
    }

    float* dsta = g_o + ((size_t)b * 512 + hwlo * 64 + ca) * 32768;
    float* dstb = g_o + ((size_t)b * 512 + hwlo * 64 + cc) * 32768;
#pragma unroll 2
    for (int n = 0; n < 8; n++) {
        const u64t* arow = (const u64t*)(attn_s + n * 1024);
#pragma unroll 4
        for (int qd = 0; qd < 32; qd++) {
            const u64t* ap = arow + qd * 16;
            u64t acca = 0ull, accb = 0ull;
#pragma unroll
            for (int jp = 0; jp < 16; jp++) {
                const u64t a = ap[jp];
                acca = fma2(a, vpa[jp], acca);
                accb = fma2(a, vpb[jp], accb);
            }
            const float2 fa = unpack2(acca);
            const float2 fb = unpack2(accb);
            dsta[qd * 1024 + n * 128 + t] = fa.x + fa.y;
            dstb[qd * 1024 + n * 128 + t] = fb.x + fb.y;
        }
    }
}

// ============================================================
// Kernel 3: proj conv as tf32 GEMM: out(256 x 32768) = Wp(256x512) * O(512x32768)
// Same corrected tiling as k_qkv; double-buffered; fused bias + layer_scale.
// ============================================================
__global__ __launch_bounds__(256) void k_proj(
    const float* __restrict__ pw, const float* __restrict__ pb,
    const float* __restrict__ ls, float* __restrict__ out)
{
    __shared__ unsigned As[2][16][136];
    __shared__ unsigned Bs[2][16][136];

    const int tid  = threadIdx.x;
    const int lane = tid & 31;
    const int warp = tid >> 5;
    const int wm = warp & 1;           // m tile (0..1) of 64 rows
    const int wn = warp >> 1;          // n tile (0..3) of 32 cols
    const int b  = blockIdx.z;
    const int m0 = blockIdx.y << 7;
    const int p0 = blockIdx.x << 7;

    const float* X = g_o + (size_t)b * 512 * P_TOT;

    const int am = tid >> 1;
    const int ak = (tid & 1) << 3;
    const int brow = tid >> 5;
    const int bcol = (tid & 31) << 2;

    const int NIT = 512 / 16;   // 32 iterations

    float acc[4][4][4];
#pragma unroll
    for (int i = 0; i < 4; i++)
#pragma unroll
        for (int j = 0; j < 4; j++)
#pragma unroll
            for (int r = 0; r < 4; r++) acc[i][j][r] = 0.f;

    float4 wa0, wa1, xb0, xb1;

    // prologue: tile 0 -> buf 0
    wa0 = *(const float4*)(pw + (size_t)(m0 + am) * 512 + ak);
    wa1 = *(const float4*)(pw + (size_t)(m0 + am) * 512 + ak + 4);
    xb0 = *(const float4*)(X + (size_t)brow * P_TOT + p0 + bcol);
    xb1 = *(const float4*)(X + (size_t)(brow + 8) * P_TOT + p0 + bcol);
    {
        As[0][ak + 0][am] = f2tf(wa0.x);
        As[0][ak + 1][am] = f2tf(wa0.y);
        As[0][ak + 2][am] = f2tf(wa0.z);
        As[0][ak + 3][am] = f2tf(wa0.w);
        As[0][ak + 4][am] = f2tf(wa1.x);
        As[0][ak + 5][am] = f2tf(wa1.y);
        As[0][ak + 6][am] = f2tf(wa1.z);
        As[0][ak + 7][am] = f2tf(wa1.w);
        uint4 u0 = make_uint4(f2tf(xb0.x), f2tf(xb0.y), f2tf(xb0.z), f2tf(xb0.w));
        uint4 u1 = make_uint4(f2tf(xb1.x), f2tf(xb1.y), f2tf(xb1.z), f2tf(xb1.w));
        *(uint4*)(&Bs[0][brow][bcol])     = u0;
        *(uint4*)(&Bs[0][brow + 8][bcol]) = u1;
    }
    __syncthreads();
    // prefetch tile 1
    wa0 = *(const float4*)(pw + (size_t)(m0 + am) * 512 + 16 + ak);
    wa1 = *(const float4*)(pw + (size_t)(m0 + am) * 512 + 16 + ak + 4);
    xb0 = *(const float4*)(X + (size_t)(16 + brow) * P_TOT + p0 + bcol);
    xb1 = *(const float4*)(X + (size_t)(16 + brow + 8) * P_TOT + p0 + bcol);

    for (int it = 0; it < NIT; it++) {
        const int cur = it & 1;
        if (it + 1 < NIT) {
            const int nxt = cur ^ 1;
            As[nxt][ak + 0][am] = f2tf(wa0.x);
            As[nxt][ak + 1][am] = f2tf(wa0.y);
            As[nxt][ak + 2][am] = f2tf(wa0.z);
            As[nxt][ak + 3][am] = f2tf(wa0.w);
            As[nxt][ak + 4][am] = f2tf(wa1.x);
            As[nxt][ak + 5][am] = f2tf(wa1.y);
            As[nxt][ak + 6][am] = f2tf(wa1.z);
            As[nxt][ak + 7][am] = f2tf(wa1.w);
            uint4 u0 = make_uint4(f2tf(xb0.x), f2tf(xb0.y), f2tf(xb0.z), f2tf(xb0.w));
            uint4 u1 = make_uint4(f2tf(xb1.x), f2tf(xb1.y), f2tf(xb1.z), f2tf(xb1.w));
            *(uint4*)(&Bs[nxt][brow][bcol])     = u0;
            *(uint4*)(&Bs[nxt][brow + 8][bcol]) = u1;
            if (it + 2 < NIT) {
                const int k2 = (it + 2) * 16;
                wa0 = *(const float4*)(pw + (size_t)(m0 + am) * 512 + k2 + ak);
                wa1 = *(const float4*)(pw + (size_t)(m0 + am) * 512 + k2 + ak + 4);
                xb0 = *(const float4*)(X + (size_t)(k2 + brow) * P_TOT + p0 + bcol);
                xb1 = *(const float4*)(X + (size_t)(k2 + brow + 8) * P_TOT + p0 + bcol);
            }
        }

#pragma unroll
        for (int ks = 0; ks < 16; ks += 8) {
            unsigned afr[4][4], bfr[4][2];
#pragma unroll
            for (int mi = 0; mi < 4; mi++) {
                const int mr = wm * 64 + mi * 16 + (lane >> 2);   // <= 127
                afr[mi][0] = As[cur][ks + (lane & 3)][mr];
                afr[mi][1] = As[cur][ks + (lane & 3)][mr + 8];
                afr[mi][2] = As[cur][ks + 4 + (lane & 3)][mr];
                afr[mi][3] = As[cur][ks + 4 + (lane & 3)][mr + 8];
            }
#pragma unroll
            for (int ni = 0; ni < 4; ni++) {
                const int nc = wn * 32 + ni * 8 + (lane >> 2);    // <= 127
                bfr[ni][0] = Bs[cur][ks + (lane & 3)][nc];
                bfr[ni][1] = Bs[cur][ks + 4 + (lane & 3)][nc];
            }
#pragma unroll
            for (int mi = 0; mi < 4; mi++)
#pragma unroll
                for (int ni = 0; ni < 4; ni++)
                    mma_tf32(acc[mi][ni][0], acc[mi][ni][1], acc[mi][ni][2], acc[mi][ni][3],
                             afr[mi][0], afr[mi][1], afr[mi][2], afr[mi][3],
                             bfr[ni][0], bfr[ni][1]);
        }
        __syncthreads();
    }

    const int lrow = lane >> 2;
    const int lcol = (lane & 3) << 1;
#pragma unroll
    for (int mi = 0; mi < 4; mi++) {
#pragma unroll
        for (int h = 0; h < 2; h++) {
            const int o = m0 + wm * 64 + mi * 16 + lrow + h * 8;   // <= m0+127
            const float bias  = pb[o];
            const float scale = ls[o];
            float* base = out + ((size_t)(b * 256 + o)) * P_TOT + p0 + wn * 32 + lcol;
#pragma unroll
            for (int ni = 0; ni < 4; ni++) {
                float2 v;
                v.x = (acc[mi][ni][h * 2 + 0] + bias) * scale;
                v.y = (acc[mi][ni][h * 2 + 1] + bias) * scale;
                *(float2*)(base + ni * 8) = v;
            }
        }
    }
}

// ============================================================
extern "C" void kernel_launch(void* const* d_in, const int* in_sizes, int n_in,
                              void* d_out, int out_size)
{
    const float* x   = (const float*)d_in[0];
    const float* qw  = (const float*)d_in[1];
    const float* qb  = (const float*)d_in[2];
    const float* kvw = (const float*)d_in[3];
    const float* kvb = (const float*)d_in[4];
    const float* pw  = (const float*)d_in[5];
    const float* pb  = (const float*)d_in[6];
    const float* ls  = (const float*)d_in[7];
    float* out = (float*)d_out;

    // 1) QKV conv (tf32 TC, double-buffered): grid (Ntiles=256, Mtiles=5, B=2)
    k_qkv<<<dim3(256, 5, 2), 256>>>(x, qw, qb, kvw, kvb);
    // 2a) Q.K^T split-K partials: (bn=16, chunks=32)
    k_qk<<<dim3(16, 32), 256>>>();
    // 2b) reduce + softmax
    k_softmax<<<16, 1024>>>();
    // 2c) attn.V, 2 channels/thread: (cb=256, b=2)
    k_av<<<dim3(256, 2), 128>>>();
    // 3) proj conv (tf32 TC, double-buffered): grid (Ntiles=256, Mtiles=2, B=2)
    k_proj<<<dim3(256, 2, 2), 256>>>(pw, pb, ls, out);
}

// round 15
// speedup vs baseline: 1.7071x; 1.0538x over previous
#include <cuda_runtime.h>
#include <cstdint>

// Problem constants
// x: (B=2, C=256, D=32, H=32, W=32); NH=8, KD=VD=64
#define C_IN   256
#define P_TOT  32768      // D*H*W per batch
#define HWX    1024       // H*W

typedef unsigned long long u64t;

// ---------------- packed f32x2 helpers (k_av) ----------------
__device__ __forceinline__ u64t fma2(u64t a, u64t b, u64t c) {
    u64t d;
    asm("fma.rn.f32x2 %0, %1, %2, %3;" : "=l"(d) : "l"(a), "l"(b), "l"(c));
    return d;
}
__device__ __forceinline__ u64t pack2(float x, float y) {
    u64t d;
    asm("mov.b64 %0, {%1, %2};" : "=l"(d) : "f"(x), "f"(y));
    return d;
}
__device__ __forceinline__ float2 unpack2(u64t v) {
    float2 f;
    asm("mov.b64 {%0, %1}, %2;" : "=f"(f.x), "=f"(f.y) : "l"(v));
    return f;
}

// ---------------- tf32 mma helpers ----------------
__device__ __forceinline__ unsigned f2tf(float f) {
    unsigned u;
    asm("cvt.rna.tf32.f32 %0, %1;" : "=r"(u) : "f"(f));
    return u;
}
__device__ __forceinline__ void mma_tf32(
    float& c0, float& c1, float& c2, float& c3,
    unsigned a0, unsigned a1, unsigned a2, unsigned a3,
    unsigned b0, unsigned b1)
{
    asm volatile(
        "mma.sync.aligned.m16n8k8.row.col.f32.tf32.tf32.f32 "
        "{%0,%1,%2,%3},{%4,%5,%6,%7},{%8,%9},{%0,%1,%2,%3};"
        : "+f"(c0), "+f"(c1), "+f"(c2), "+f"(c3)
        : "r"(a0), "r"(a1), "r"(a2), "r"(a3), "r"(b0), "r"(b1));
}

// ---------------- scratch (device globals, no allocation) ----------------
// q_s[b][n][qd][c][hw]
__device__ float g_q[33554432];   // 2*8*32*64*1024
// k_s[b][kd][c][hw]
__device__ float g_k[4194304];    // 2*32*64*1024
// v_s[b][kd][c][hw]
__device__ float g_v[4194304];
// split-K partials of S: [bn][chunk][qd][kd]
__device__ float g_sp[524288];    // 16*32*32*32
// attn[bn][qd][kd]
__device__ float g_attn[16384];
// o_s[b][ch][d][hw']  — proj input, torch-reshape permutation already applied
__device__ float g_o[33554432];   // 2*512*32768

// ============================================================
// Kernel 1: fused QKV conv as tf32 tensor-core GEMM
//   Y(640 x 32768) = W(640x256) * X(256x32768)
// Grid (Mtiles=5, Ntiles=256, B=2): m varies FASTEST so same-p0 blocks are
// concurrent and share the X tile through L2 (x DRAM ~134MB instead of ~670MB).
// Block 128x128, BK=16, 256 threads = 8 warps; warp tile 64(M)x32(N):
// wm = warp&1 (stride 64), wn = warp>>1 (stride 32), 4x4 m16n8k8 per k8-step.
// Double-buffered smem + register prefetch; pitch 136 conflict-free.
// ============================================================
__global__ __launch_bounds__(256) void k_qkv(
    const float* __restrict__ x,
    const float* __restrict__ qw, const float* __restrict__ qb,
    const float* __restrict__ kvw, const float* __restrict__ kvb)
{
    __shared__ unsigned As[2][16][136];   // [buf][k][m] tf32 bits
    __shared__ unsigned Bs[2][16][136];   // [buf][k][n] tf32 bits

    const int tid  = threadIdx.x;
    const int lane = tid & 31;
    const int warp = tid >> 5;
    const int wm = warp & 1;           // m tile (0..1) of 64 rows
    const int wn = warp >> 1;          // n tile (0..3) of 32 cols
    const int b  = blockIdx.z;
    const int m0 = blockIdx.x << 7;    // m fastest
    const int p0 = blockIdx.y << 7;

    const float* Wsrc;
    int mb;
    if (m0 < 512) { Wsrc = qw;  mb = m0; }
    else          { Wsrc = kvw; mb = m0 - 512; }

    const float* X = x + (size_t)b * C_IN * P_TOT;

    // loaders
    const int am = tid >> 1;              // 0..127 (W row)
    const int ak = (tid & 1) << 3;        // 0 or 8 (k offset)
    const int brow = tid >> 5;            // 0..7   (k row; also brow+8)
    const int bcol = (tid & 31) << 2;     // 0..124

    const int NIT = C_IN / 16;            // 16 iterations

    float acc[4][4][4];
#pragma unroll
    for (int i = 0; i < 4; i++)
#pragma unroll
        for (int j = 0; j < 4; j++)
#pragma unroll
            for (int r = 0; r < 4; r++) acc[i][j][r] = 0.f;

    float4 wa0, wa1, xb0, xb1;

    // ---- prologue: tile 0 -> smem buf 0 ----
    wa0 = *(const float4*)(Wsrc + (size_t)(mb + am) * C_IN + ak);
    wa1 = *(const float4*)(Wsrc + (size_t)(mb + am) * C_IN + ak + 4);
    xb0 = *(const float4*)(X + (size_t)brow * P_TOT + p0 + bcol);
    xb1 = *(const float4*)(X + (size_t)(brow + 8) * P_TOT + p0 + bcol);
    {
        As[0][ak + 0][am] = f2tf(wa0.x);
        As[0][ak + 1][am] = f2tf(wa0.y);
        As[0][ak + 2][am] = f2tf(wa0.z);
        As[0][ak + 3][am] = f2tf(wa0.w);
        As[0][ak + 4][am] = f2tf(wa1.x);
        As[0][ak + 5][am] = f2tf(wa1.y);
        As[0][ak + 6][am] = f2tf(wa1.z);
        As[0][ak + 7][am] = f2tf(wa1.w);
        uint4 u0 = make_uint4(f2tf(xb0.x), f2tf(xb0.y), f2tf(xb0.z), f2tf(xb0.w));
        uint4 u1 = make_uint4(f2tf(xb1.x), f2tf(xb1.y), f2tf(xb1.z), f2tf(xb1.w));
        *(uint4*)(&Bs[0][brow][bcol])     = u0;
        *(uint4*)(&Bs[0][brow + 8][bcol]) = u1;
    }
    __syncthreads();
    // prefetch tile 1 into regs
    wa0 = *(const float4*)(Wsrc + (size_t)(mb + am) * C_IN + 16 + ak);
    wa1 = *(const float4*)(Wsrc + (size_t)(mb + am) * C_IN + 16 + ak + 4);
    xb0 = *(const float4*)(X + (size_t)(16 + brow) * P_TOT + p0 + bcol);
    xb1 = *(const float4*)(X + (size_t)(16 + brow + 8) * P_TOT + p0 + bcol);

    for (int it = 0; it < NIT; it++) {
        const int cur = it & 1;
        if (it + 1 < NIT) {
            const int nxt = cur ^ 1;
            // store tile it+1 (in regs) into the other buffer
            As[nxt][ak + 0][am] = f2tf(wa0.x);
            As[nxt][ak + 1][am] = f2tf(wa0.y);
            As[nxt][ak + 2][am] = f2tf(wa0.z);
            As[nxt][ak + 3][am] = f2tf(wa0.w);
            As[nxt][ak + 4][am] = f2tf(wa1.x);
            As[nxt][ak + 5][am] = f2tf(wa1.y);
            As[nxt][ak + 6][am] = f2tf(wa1.z);
            As[nxt][ak + 7][am] = f2tf(wa1.w);
            uint4 u0 = make_uint4(f2tf(xb0.x), f2tf(xb0.y), f2tf(xb0.z), f2tf(xb0.w));
            uint4 u1 = make_uint4(f2tf(xb1.x), f2tf(xb1.y), f2tf(xb1.z), f2tf(xb1.w));
            *(uint4*)(&Bs[nxt][brow][bcol])     = u0;
            *(uint4*)(&Bs[nxt][brow + 8][bcol]) = u1;
            if (it + 2 < NIT) {   // prefetch tile it+2 into regs
                const int k2 = (it + 2) * 16;
                wa0 = *(const float4*)(Wsrc + (size_t)(mb + am) * C_IN + k2 + ak);
                wa1 = *(const float4*)(Wsrc + (size_t)(mb + am) * C_IN + k2 + ak + 4);
                xb0 = *(const float4*)(X + (size_t)(k2 + brow) * P_TOT + p0 + bcol);
                xb1 = *(const float4*)(X + (size_t)(k2 + brow + 8) * P_TOT + p0 + bcol);
            }
        }

#pragma unroll
        for (int ks = 0; ks < 16; ks += 8) {
            unsigned afr[4][4], bfr[4][2];
#pragma unroll
            for (int mi = 0; mi < 4; mi++) {
                const int mr = wm * 64 + mi * 16 + (lane >> 2);   // <= 127
                afr[mi][0] = As[cur][ks + (lane & 3)][mr];
                afr[mi][1] = As[cur][ks + (lane & 3)][mr + 8];
                afr[mi][2] = As[cur][ks + 4 + (lane & 3)][mr];
                afr[mi][3] = As[cur][ks + 4 + (lane & 3)][mr + 8];
            }
#pragma unroll
            for (int ni = 0; ni < 4; ni++) {
                const int nc = wn * 32 + ni * 8 + (lane >> 2);    // <= 127
                bfr[ni][0] = Bs[cur][ks + (lane & 3)][nc];
                bfr[ni][1] = Bs[cur][ks + 4 + (lane & 3)][nc];
            }
#pragma unroll
            for (int mi = 0; mi < 4; mi++)
#pragma unroll
                for (int ni = 0; ni < 4; ni++)
                    mma_tf32(acc[mi][ni][0], acc[mi][ni][1], acc[mi][ni][2], acc[mi][ni][3],
                             afr[mi][0], afr[mi][1], afr[mi][2], afr[mi][3],
                             bfr[ni][0], bfr[ni][1]);
        }
        __syncthreads();
    }

    // epilogue: scatter rows into g_q/g_k/g_v (layout-fused)
    const int d    = p0 >> 10;      // one d per block
    const int hw0  = p0 & 1023;
    const int lrow = lane >> 2;
    const int lcol = (lane & 3) << 1;
#pragma unroll
    for (int mi = 0; mi < 4; mi++) {
#pragma unroll
        for (int h = 0; h < 2; h++) {
            const int o = m0 + wm * 64 + mi * 16 + lrow + h * 8;   // <= m0+127
            float bias;
            float* dst;
            if (o < 512) {                      // q: n = o>>6, c = o&63
                bias = qb[o];
                const int n = o >> 6, c = o & 63;
                dst = g_q + ((((size_t)b * 8 + n) * 32 + d) * 64 + c) * 1024;
            } else if (o < 576) {               // k
                bias = kvb[o - 512];
                const int c = o - 512;
                dst = g_k + (((size_t)b * 32 + d) * 64 + c) * 1024;
            } else {                            // v
                bias = kvb[o - 512];
                const int c = o - 576;
                dst = g_v + (((size_t)b * 32 + d) * 64 + c) * 1024;
            }
            float* base = dst + hw0 + wn * 32 + lcol;
#pragma unroll
            for (int ni = 0; ni < 4; ni++) {
                float2 v;
                v.x = acc[mi][ni][h * 2 + 0] + bias;
                v.y = acc[mi][ni][h * 2 + 1] + bias;
                *(float2*)(base + ni * 8) = v;
            }
        }
    }
}

// ============================================================
// Kernel 2a: S_partial[bn][chunk] = Q(32 x 2048chunk) * K^T  (split-K, fp32)
// float4 smem fragment loads (pitch 68 for 16B alignment).
// ============================================================
__global__ __launch_bounds__(256) void k_qk()
{
    __shared__ float Qs[32][68];
    __shared__ float Ks[32][68];

    const int tid = threadIdx.x;
    const int tx = tid & 15, ty = tid >> 4;
    const int bn = blockIdx.x;      // b*8+n
    const int chunk = blockIdx.y;   // 0..31
    const int b = bn >> 3;

    const float* Q  = g_q + (size_t)bn * 32 * 65536;  // [qd][f]
    const float* Kp = g_k + (size_t)b  * 32 * 65536;  // [kd][f]
    const int f0 = chunk * 2048;

    float a00 = 0.f, a01 = 0.f, a10 = 0.f, a11 = 0.f;

    for (int ft = 0; ft < 2048; ft += 64) {
#pragma unroll
        for (int e = 0; e < 8; e++) {
            const int idx = tid + e * 256;
            const int r = idx >> 6, fi = idx & 63;
            Qs[r][fi] = Q [(size_t)r * 65536 + f0 + ft + fi];
            Ks[r][fi] = Kp[(size_t)r * 65536 + f0 + ft + fi];
        }
        __syncthreads();
#pragma unroll
        for (int ff = 0; ff < 64; ff += 4) {
            const float4 q0 = *(const float4*)(&Qs[ty][ff]);
            const float4 q1 = *(const float4*)(&Qs[ty + 16][ff]);
            const float4 k0 = *(const float4*)(&Ks[tx][ff]);
            const float4 k1 = *(const float4*)(&Ks[tx + 16][ff]);
            a00 += q0.x * k0.x; a00 += q0.y * k0.y; a00 += q0.z * k0.z; a00 += q0.w * k0.w;
            a01 += q0.x * k1.x; a01 += q0.y * k1.y; a01 += q0.z * k1.z; a01 += q0.w * k1.w;
            a10 += q1.x * k0.x; a10 += q1.y * k0.y; a10 += q1.z * k0.z; a10 += q1.w * k0.w;
            a11 += q1.x * k1.x; a11 += q1.y * k1.y; a11 += q1.z * k1.z; a11 += q1.w * k1.w;
        }
        __syncthreads();
    }

    float* S = g_sp + ((size_t)bn * 32 + chunk) * 1024;  // [qd][kd]
    S[ty * 32 + tx]             = a00;
    S[ty * 32 + tx + 16]        = a01;
    S[(ty + 16) * 32 + tx]      = a10;
    S[(ty + 16) * 32 + tx + 16] = a11;
}

// ============================================================
// Kernel 2b: reduce split-K partials, scale, softmax over kd (warp = one row)
// ============================================================
__global__ __launch_bounds__(1024) void k_softmax()
{
    const int bn = blockIdx.x;
    const int qd = threadIdx.x >> 5;
    const int kd = threadIdx.x & 31;

    float s = 0.f;
    for (int ch = 0; ch < 32; ch++)
        s += g_sp[((size_t)bn * 32 + ch) * 1024 + qd * 32 + kd];
    s *= 0.125f;   // VD^-0.5

    float m = s;
#pragma unroll
    for (int o = 16; o > 0; o >>= 1)
        m = fmaxf(m, __shfl_xor_sync(0xffffffffu, m, o));
    const float e = expf(s - m);
    float sum = e;
#pragma unroll
    for (int o = 16; o > 0; o >>= 1)
        sum += __shfl_xor_sync(0xffffffffu, sum, o);

    g_attn[(size_t)bn * 1024 + qd * 32 + kd] = e / sum;
}

// ============================================================
// Kernel 2c: O = attn * V (FFMA2), split over heads for occupancy:
// grid (n=8 FASTEST so same-v blocks are L2-concurrent, cb=256, b=2), 128 thr.
// Each thread: 2 channels (c, c+32), one head n, all 32 qd.
// Output in torch-reshape-permuted proj-input layout:
//   dst channel ch = hwlo*64 + c; thread t owns hw = t*8 + hwlo, hw' = n*128 + t.
// ============================================================
__global__ __launch_bounds__(128) void k_av()
{
    __shared__ float attn_s[1024];   // [qd][kd] for this (b,n)
    const int t  = threadIdx.x;      // g = hw/8
    const int n  = blockIdx.x;       // 0..7 (fastest)
    const int cb = blockIdx.y;       // 0..255: (hwlo, cpair)
    const int b  = blockIdx.z;

    for (int i = t; i < 1024; i += 128)
        attn_s[i] = g_attn[(size_t)b * 8192 + n * 1024 + i];
    __syncthreads();

    const int cpair = cb & 31;       // c_a = cpair, c_b = cpair+32
    const int hwlo  = cb >> 5;
    const int hw    = t * 8 + hwlo;
    const int ca = cpair, cc = cpair + 32;

    u64t vpa[16], vpb[16];
#pragma unroll
    for (int jp = 0; jp < 16; jp++) {
        const size_t base0 = (((size_t)b * 32 + 2 * jp)     * 64) * 1024 + hw;
        const size_t base1 = (((size_t)b * 32 + 2 * jp + 1) * 64) * 1024 + hw;
        vpa[jp] = pack2(g_v[base0 + (size_t)ca * 1024], g_v[base1 + (size_t)ca * 1024]);
        vpb[jp] = pack2(g_v[base0 + (size_t)cc * 1024], g_v[base1 + (size_t)cc * 1024]);
    }

    float* dsta = g_o + ((size_t)b * 512 + hwlo * 64 + ca) * 32768 + n * 128 + t;
    float* dstb = g_o + ((size_t)b * 512 + hwlo * 64 + cc) * 32768 + n * 128 + t;
    const u64t* arow = (const u64t*)attn_s;
#pragma unroll 8
    for (int qd = 0; qd < 32; qd++) {
        const u64t* ap = arow + qd * 16;
        u64t acca = 0ull, accb = 0ull;
#pragma unroll
        for (int jp = 0; jp < 16; jp++) {
            const u64t a = ap[jp];
            acca = fma2(a, vpa[jp], acca);
            accb = fma2(a, vpb[jp], accb);
        }
        const float2 fa = unpack2(acca);
        const float2 fb = unpack2(accb);
        dsta[qd * 1024] = fa.x + fa.y;
        dstb[qd * 1024] = fb.x + fb.y;
    }
}

// ============================================================
// Kernel 3: proj conv as tf32 GEMM: out(256 x 32768) = Wp(256x512) * O(512x32768)
// Grid (Mtiles=2, Ntiles=256, B=2) — m fastest for g_o L2 reuse.
// Same corrected tiling as k_qkv; double-buffered; fused bias + layer_scale.
// ============================================================
__global__ __launch_bounds__(256) void k_proj(
    const float* __restrict__ pw, const float* __restrict__ pb,
    const float* __restrict__ ls, float* __restrict__ out)
{
    __shared__ unsigned As[2][16][136];
    __shared__ unsigned Bs[2][16][136];

    const int tid  = threadIdx.x;
    const int lane = tid & 31;
    const int warp = tid >> 5;
    const int wm = warp & 1;           // m tile (0..1) of 64 rows
    const int wn = warp >> 1;          // n tile (0..3) of 32 cols
    const int b  = blockIdx.z;
    const int m0 = blockIdx.x << 7;    // m fastest
    const int p0 = blockIdx.y << 7;

    const float* X = g_o + (size_t)b * 512 * P_TOT;

    const int am = tid >> 1;
    const int ak = (tid & 1) << 3;
    const int brow = tid >> 5;
    const int bcol = (tid & 31) << 2;

    const int NIT = 512 / 16;   // 32 iterations

    float acc[4][4][4];
#pragma unroll
    for (int i = 0; i < 4; i++)
#pragma unroll
        for (int j = 0; j < 4; j++)
#pragma unroll
            for (int r = 0; r < 4; r++) acc[i][j][r] = 0.f;

    float4 wa0, wa1, xb0, xb1;

    // prologue: tile 0 -> buf 0
    wa0 = *(const float4*)(pw + (size_t)(m0 + am) * 512 + ak);
    wa1 = *(const float4*)(pw + (size_t)(m0 + am) * 512 + ak + 4);
    xb0 = *(const float4*)(X + (size_t)brow * P_TOT + p0 + bcol);
    xb1 = *(const float4*)(X + (size_t)(brow + 8) * P_TOT + p0 + bcol);
    {
        As[0][ak + 0][am] = f2tf(wa0.x);
        As[0][ak + 1][am] = f2tf(wa0.y);
        As[0][ak + 2][am] = f2tf(wa0.z);
        As[0][ak + 3][am] = f2tf(wa0.w);
        As[0][ak + 4][am] = f2tf(wa1.x);
        As[0][ak + 5][am] = f2tf(wa1.y);
        As[0][ak + 6][am] = f2tf(wa1.z);
        As[0][ak + 7][am] = f2tf(wa1.w);
        uint4 u0 = make_uint4(f2tf(xb0.x), f2tf(xb0.y), f2tf(xb0.z), f2tf(xb0.w));
        uint4 u1 = make_uint4(f2tf(xb1.x), f2tf(xb1.y), f2tf(xb1.z), f2tf(xb1.w));
        *(uint4*)(&Bs[0][brow][bcol])     = u0;
        *(uint4*)(&Bs[0][brow + 8][bcol]) = u1;
    }
    __syncthreads();
    // prefetch tile 1
    wa0 = *(const float4*)(pw + (size_t)(m0 + am) * 512 + 16 + ak);
    wa1 = *(const float4*)(pw + (size_t)(m0 + am) * 512 + 16 + ak + 4);
    xb0 = *(const float4*)(X + (size_t)(16 + brow) * P_TOT + p0 + bcol);
    xb1 = *(const float4*)(X + (size_t)(16 + brow + 8) * P_TOT + p0 + bcol);

    for (int it = 0; it < NIT; it++) {
        const int cur = it & 1;
        if (it + 1 < NIT) {
            const int nxt = cur ^ 1;
            As[nxt][ak + 0][am] = f2tf(wa0.x);
            As[nxt][ak + 1][am] = f2tf(wa0.y);
            As[nxt][ak + 2][am] = f2tf(wa0.z);
            As[nxt][ak + 3][am] = f2tf(wa0.w);
            As[nxt][ak + 4][am] = f2tf(wa1.x);
            As[nxt][ak + 5][am] = f2tf(wa1.y);
            As[nxt][ak + 6][am] = f2tf(wa1.z);
            As[nxt][ak + 7][am] = f2tf(wa1.w);
            uint4 u0 = make_uint4(f2tf(xb0.x), f2tf(xb0.y), f2tf(xb0.z), f2tf(xb0.w));
            uint4 u1 = make_uint4(f2tf(xb1.x), f2tf(xb1.y), f2tf(xb1.z), f2tf(xb1.w));
            *(uint4*)(&Bs[nxt][brow][bcol])     = u0;
            *(uint4*)(&Bs[nxt][brow + 8][bcol]) = u1;
            if (it + 2 < NIT) {
                const int k2 = (it + 2) * 16;
                wa0 = *(const float4*)(pw + (size_t)(m0 + am) * 512 + k2 + ak);
                wa1 = *(const float4*)(pw + (size_t)(m0 + am) * 512 + k2 + ak + 4);
                xb0 = *(const float4*)(X + (size_t)(k2 + brow) * P_TOT + p0 + bcol);
                xb1 = *(const float4*)(X + (size_t)(k2 + brow + 8) * P_TOT + p0 + bcol);
            }
        }

#pragma unroll
        for (int ks = 0; ks < 16; ks += 8) {
            unsigned afr[4][4], bfr[4][2];
#pragma unroll
            for (int mi = 0; mi < 4; mi++) {
                const int mr = wm * 64 + mi * 16 + (lane >> 2);   // <= 127
                afr[mi][0] = As[cur][ks + (lane & 3)][mr];
                afr[mi][1] = As[cur][ks + (lane & 3)][mr + 8];
                afr[mi][2] = As[cur][ks + 4 + (lane & 3)][mr];
                afr[mi][3] = As[cur][ks + 4 + (lane & 3)][mr + 8];
            }
#pragma unroll
            for (int ni = 0; ni < 4; ni++) {
                const int nc = wn * 32 + ni * 8 + (lane >> 2);    // <= 127
                bfr[ni][0] = Bs[cur][ks + (lane & 3)][nc];
                bfr[ni][1] = Bs[cur][ks + 4 + (lane & 3)][nc];
            }
#pragma unroll
            for (int mi = 0; mi < 4; mi++)
#pragma unroll
                for (int ni = 0; ni < 4; ni++)
                    mma_tf32(acc[mi][ni][0], acc[mi][ni][1], acc[mi][ni][2], acc[mi][ni][3],
                             afr[mi][0], afr[mi][1], afr[mi][2], afr[mi][3],
                             bfr[ni][0], bfr[ni][1]);
        }
        __syncthreads();
    }

    const int lrow = lane >> 2;
    const int lcol = (lane & 3) << 1;
#pragma unroll
    for (int mi = 0; mi < 4; mi++) {
#pragma unroll
        for (int h = 0; h < 2; h++) {
            const int o = m0 + wm * 64 + mi * 16 + lrow + h * 8;   // <= m0+127
            const float bias  = pb[o];
            const float scale = ls[o];
            float* base = out + ((size_t)(b * 256 + o)) * P_TOT + p0 + wn * 32 + lcol;
#pragma unroll
            for (int ni = 0; ni < 4; ni++) {
                float2 v;
                v.x = (acc[mi][ni][h * 2 + 0] + bias) * scale;
                v.y = (acc[mi][ni][h * 2 + 1] + bias) * scale;
                *(float2*)(base + ni * 8) = v;
            }
        }
    }
}

// ============================================================
extern "C" void kernel_launch(void* const* d_in, const int* in_sizes, int n_in,
                              void* d_out, int out_size)
{
    const float* x   = (const float*)d_in[0];
    const float* qw  = (const float*)d_in[1];
    const float* qb  = (const float*)d_in[2];
    const float* kvw = (const float*)d_in[3];
    const float* kvb = (const float*)d_in[4];
    const float* pw  = (const float*)d_in[5];
    const float* pb  = (const float*)d_in[6];
    const float* ls  = (const float*)d_in[7];
    float* out = (float*)d_out;

    // 1) QKV conv (tf32 TC, double-buffered): grid (Mtiles=5, Ntiles=256, B=2)
    k_qkv<<<dim3(5, 256, 2), 256>>>(x, qw, qb, kvw, kvb);
    // 2a) Q.K^T split-K partials: (bn=16, chunks=32)
    k_qk<<<dim3(16, 32), 256>>>();
    // 2b) reduce + softmax
    k_softmax<<<16, 1024>>>();
    // 2c) attn.V, per-head blocks: (n=8, cb=256, b=2)
    k_av<<<dim3(8, 256, 2), 128>>>();
    // 3) proj conv (tf32 TC, double-buffered): grid (Mtiles=2, Ntiles=256, B=2)
    k_proj<<<dim3(2, 256, 2), 256>>>(pw, pb, ls, out);
}